// round 13
// baseline (speedup 1.0000x reference)
#include <cuda_runtime.h>
#include <cuda_bf16.h>
#include <cstdint>

#define Bn 16
#define Cn 256
#define Hn 96
#define Wn 96
#define HWc 9216
#define CHWc 2359296   // Cn*HWc
#define TOTc 37748736  // Bn*CHWc

// ---------------- scratch ----------------
__device__ float g_xp[TOTc];
__device__ float g_gate[TOTc];
__device__ float g_sw[TOTc];
__device__ float g_sh[TOTc];
__device__ float g_fd[TOTc];
__device__ float g_o1[TOTc];
__device__ float g_ss1[Bn*Cn*2];
__device__ float g_ss2[Bn*Cn*2];
__device__ __nv_bfloat16 g_bth[TOTc];       // B transposed [b][n][k], hi
__device__ __nv_bfloat16 g_btl[TOTc];       // lo
__device__ __nv_bfloat16 g_ahh[3*Cn*Cn];    // A hi (in_w, gate_w, pw_w)
__device__ __nv_bfloat16 g_all[3*Cn*Cn];    // A lo

__device__ __forceinline__ float sigmoid_f(float x) { return 1.0f / (1.0f + __expf(-x)); }
__device__ __forceinline__ float silu_f(float x)    { return x / (1.0f + __expf(-x)); }

__device__ __forceinline__ uint32_t smem_u32(const void* p) {
    uint32_t a;
    asm("{ .reg .u64 t; cvta.to.shared.u64 t, %1; cvt.u32.u64 %0, t; }" : "=r"(a) : "l"(p));
    return a;
}
__device__ __forceinline__ void ldsm4(uint32_t &r0, uint32_t &r1, uint32_t &r2, uint32_t &r3, uint32_t addr) {
    asm volatile("ldmatrix.sync.aligned.m8n8.x4.shared.b16 {%0,%1,%2,%3}, [%4];"
                 : "=r"(r0), "=r"(r1), "=r"(r2), "=r"(r3) : "r"(addr));
}
__device__ __forceinline__ void mma16816(float* d, const uint32_t* a, const uint32_t* b) {
    asm volatile("mma.sync.aligned.m16n8k16.row.col.f32.bf16.bf16.f32 "
                 "{%0,%1,%2,%3}, {%4,%5,%6,%7}, {%8,%9}, {%0,%1,%2,%3};"
                 : "+f"(d[0]), "+f"(d[1]), "+f"(d[2]), "+f"(d[3])
                 : "r"(a[0]), "r"(a[1]), "r"(a[2]), "r"(a[3]), "r"(b[0]), "r"(b[1]));
}
__device__ __forceinline__ void cpa16(uint32_t sm, const void* g) {
    asm volatile("cp.async.cg.shared.global [%0], [%1], 16;" :: "r"(sm), "l"(g));
}
#define CPA_COMMIT() asm volatile("cp.async.commit_group;" ::: "memory")
#define CPA_WAIT1()  asm volatile("cp.async.wait_group 1;" ::: "memory")
#define CPA_WAIT0()  asm volatile("cp.async.wait_group 0;" ::: "memory")

// ================ conversion kernels ================
__global__ __launch_bounds__(256) void convA3_kernel(const float* __restrict__ w0,
                                                     const float* __restrict__ w1,
                                                     const float* __restrict__ w2,
                                                     __nv_bfloat16* __restrict__ ah,
                                                     __nv_bfloat16* __restrict__ al)
{
    int i = blockIdx.x * 256 + threadIdx.x;
    int which = i >> 16, j = i & 65535;
    const float* s = (which == 0) ? w0 : ((which == 1) ? w1 : w2);
    float v = s[j];
    __nv_bfloat16 h = __float2bfloat16(v);
    ah[i] = h;
    al[i] = __float2bfloat16(v - __bfloat162float(h));
}

// src fp32 [b][K=256][N=9216] -> bh/bl bf16 [b][N=9216][K=256]; mode1: silu(affine) via ss
__global__ __launch_bounds__(256) void convT_kernel(const float* __restrict__ src,
                                                    __nv_bfloat16* __restrict__ bh,
                                                    __nv_bfloat16* __restrict__ bl,
                                                    const float* __restrict__ ss, int mode)
{
    __shared__ float t[32][33];
    const int n0 = blockIdx.x * 32, k0 = blockIdx.y * 32, bb = blockIdx.z;
    const int tx = threadIdx.x, ty = threadIdx.y;
#pragma unroll
    for (int i = 0; i < 4; i++) {
        int k = k0 + ty + 8 * i;
        float v = src[(size_t)bb * CHWc + (size_t)k * HWc + n0 + tx];
        if (mode) {
            float2 sc = *(const float2*)&ss[(bb * Cn + k) * 2];
            v = silu_f(fmaf(v, sc.x, sc.y));
        }
        t[ty + 8 * i][tx] = v;
    }
    __syncthreads();
#pragma unroll
    for (int i = 0; i < 4; i++) {
        int n = n0 + ty + 8 * i;
        float v = t[tx][ty + 8 * i];
        __nv_bfloat16 h = __float2bfloat16(v);
        size_t o = (size_t)bb * CHWc + (size_t)n * Cn + k0 + tx;
        bh[o] = h;
        bl[o] = __float2bfloat16(v - __bfloat162float(h));
    }
}

// ================ k-folded bf16 warp-MMA GEMM, 3-stage pipeline ================
// C[b][m][n] = sum_k A[m][k]*Bt[b][n][k]. BM=128, BN=128, BK=32.
// 512 threads = 16 warps (4m x 4n), warp tile 32x32. 8 k-iters; per fragment load,
// 3 products (Ah*Bh, Al*Bh, Ah*Bl). One __syncthreads per iter (3-stage ring).
#define PITCH 40                 // bf16/row: 80B stride, conflict-free ldmatrix
#define TILE_B (128 * PITCH * 2) // 10240 bytes per (array, stage)
#define OFF_AH 0
#define OFF_AL TILE_B
#define OFF_BH (2*TILE_B)
#define OFF_BL (3*TILE_B)
#define STG (4*TILE_B)           // 40960
#define GSM_TOT (3*STG)          // 122880

__global__ __launch_bounds__(512) void gemm_mma_kernel(
    const __nv_bfloat16* __restrict__ Ah, const __nv_bfloat16* __restrict__ Al,
    const __nv_bfloat16* __restrict__ Bh, const __nv_bfloat16* __restrict__ Bl,
    float* __restrict__ Cd, const float* __restrict__ gbias, int mode)
{
    extern __shared__ __align__(16) char gsm[];
    const uint32_t su = smem_u32(gsm);
    const int tid = threadIdx.x, lane = tid & 31, warp = tid >> 5;
    const int wm = (warp & 3) * 32, wn = (warp >> 2) * 32;
    const int n0 = blockIdx.x * 128, bm = blockIdx.y * 128, bb = blockIdx.z;

    // staging: thread t -> row = t>>2 (0..127), 16B chunk = t&3
    const int s_r = tid >> 2, s_c = (tid & 3);
    const uint32_t s_off = (uint32_t)(s_r * (PITCH * 2) + s_c * 16);
    const size_t a_go = (size_t)(bm + s_r) * 256 + s_c * 8;
    const size_t b_go = ((size_t)bb * HWc + n0 + s_r) * 256 + s_c * 8;

    float acc[2][4][4];
#pragma unroll
    for (int i = 0; i < 2; i++)
#pragma unroll
        for (int j = 0; j < 4; j++)
#pragma unroll
            for (int k = 0; k < 4; k++) acc[i][j][k] = 0.0f;

    // prologue: stages 0 and 1
#pragma unroll
    for (int pre = 0; pre < 2; pre++) {
        const uint32_t sb = su + pre * STG;
        const int k0 = pre * 32;
        cpa16(sb + OFF_AH + s_off, Ah + a_go + k0);
        cpa16(sb + OFF_AL + s_off, Al + a_go + k0);
        cpa16(sb + OFF_BH + s_off, Bh + b_go + k0);
        cpa16(sb + OFF_BL + s_off, Bl + b_go + k0);
        CPA_COMMIT();
    }

    int rd = 0, wr = 2;
    for (int it = 0; it < 8; it++) {
        if (it < 7) CPA_WAIT1(); else CPA_WAIT0();
        __syncthreads();
        // issue load for it+2 into stage wr (distinct from rd and rd+1; prior
        // readers of wr finished before the barrier above)
        if (it < 6) {
            const uint32_t sw = su + wr * STG;
            const int k0 = (it + 2) * 32;
            cpa16(sw + OFF_AH + s_off, Ah + a_go + k0);
            cpa16(sw + OFF_AL + s_off, Al + a_go + k0);
            cpa16(sw + OFF_BH + s_off, Bh + b_go + k0);
            cpa16(sw + OFF_BL + s_off, Bl + b_go + k0);
            CPA_COMMIT();
        }
        const uint32_t sb = su + rd * STG;
#pragma unroll
        for (int ks = 0; ks < 2; ks++) {
            uint32_t ahf[2][4], alf[2][4], bhf[4][2], blf[4][2];
#pragma unroll
            for (int mt = 0; mt < 2; mt++) {
                uint32_t ao = (uint32_t)(((wm + mt * 16 + (lane & 15)) * PITCH
                                          + ks * 16 + (lane >> 4) * 8) << 1);
                ldsm4(ahf[mt][0], ahf[mt][1], ahf[mt][2], ahf[mt][3], sb + OFF_AH + ao);
                ldsm4(alf[mt][0], alf[mt][1], alf[mt][2], alf[mt][3], sb + OFF_AL + ao);
            }
            // B: one ldsm4 covers two n-tiles (bit4 of lane -> +8 rows, bit3 -> +8 cols)
#pragma unroll
            for (int ntp = 0; ntp < 2; ntp++) {
                uint32_t bo = (uint32_t)(((wn + ntp * 16 + ((lane >> 4) & 1) * 8 + (lane & 7)) * PITCH
                                          + ks * 16 + ((lane >> 3) & 1) * 8) << 1);
                ldsm4(bhf[2*ntp][0], bhf[2*ntp][1], bhf[2*ntp+1][0], bhf[2*ntp+1][1], sb + OFF_BH + bo);
                ldsm4(blf[2*ntp][0], blf[2*ntp][1], blf[2*ntp+1][0], blf[2*ntp+1][1], sb + OFF_BL + bo);
            }
#pragma unroll
            for (int mt = 0; mt < 2; mt++)
#pragma unroll
                for (int nt = 0; nt < 4; nt++) {
                    mma16816(acc[mt][nt], ahf[mt], bhf[nt]);
                    mma16816(acc[mt][nt], alf[mt], bhf[nt]);
                    mma16816(acc[mt][nt], ahf[mt], blf[nt]);
                }
        }
        if (++rd == 3) rd = 0;
        if (++wr == 3) wr = 0;
    }

    // epilogue: fragment rows lane/4 (+8), cols 2*(lane%4)+{0,1}
    const int gr = lane >> 2, gc = (lane & 3) * 2;
#pragma unroll
    for (int mt = 0; mt < 2; mt++) {
        const int row0 = bm + wm + mt * 16 + gr;
        float* p0 = Cd + (size_t)bb * CHWc + (size_t)row0 * HWc + n0 + wn;
        float* p1 = p0 + (size_t)8 * HWc;
        if (mode == 0) {
#pragma unroll
            for (int nt = 0; nt < 4; nt++) {
                *(float2*)(p0 + nt * 8 + gc) = make_float2(acc[mt][nt][0], acc[mt][nt][1]);
                *(float2*)(p1 + nt * 8 + gc) = make_float2(acc[mt][nt][2], acc[mt][nt][3]);
            }
        } else {
            const float gb0 = gbias[row0], gb1 = gbias[row0 + 8];
#pragma unroll
            for (int nt = 0; nt < 4; nt++) {
                *(float2*)(p0 + nt * 8 + gc) =
                    make_float2(sigmoid_f(acc[mt][nt][0] + gb0), sigmoid_f(acc[mt][nt][1] + gb0));
                *(float2*)(p1 + nt * 8 + gc) =
                    make_float2(sigmoid_f(acc[mt][nt][2] + gb1), sigmoid_f(acc[mt][nt][3] + gb1));
            }
        }
    }
}

// ---------------- GroupNorm stats -> per-(b,c) affine ----------------
__global__ __launch_bounds__(1024) void gn_stats_kernel(const float* __restrict__ src,
                                                        const float* __restrict__ gamma,
                                                        const float* __restrict__ beta,
                                                        float* __restrict__ ss)
{
    const int g = blockIdx.x, b = blockIdx.y, tid = threadIdx.x;
    const float4* p = (const float4*)(src + (size_t)b * CHWc + (size_t)g * 16 * HWc);
    float s = 0.0f, s2 = 0.0f;
    const int n4 = 16 * HWc / 4;
    for (int i = tid; i < n4; i += 1024) {
        float4 v = p[i];
        s  += v.x + v.y + v.z + v.w;
        s2 += v.x * v.x + v.y * v.y + v.z * v.z + v.w * v.w;
    }
#pragma unroll
    for (int off = 16; off > 0; off >>= 1) {
        s  += __shfl_xor_sync(0xffffffffu, s, off);
        s2 += __shfl_xor_sync(0xffffffffu, s2, off);
    }
    __shared__ float ws[32], ws2[32];
    __shared__ float mean_s, rstd_s;
    const int wid = tid >> 5, lane = tid & 31;
    if (lane == 0) { ws[wid] = s; ws2[wid] = s2; }
    __syncthreads();
    if (tid < 32) {
        float ts = ws[tid], ts2 = ws2[tid];
#pragma unroll
        for (int off = 16; off > 0; off >>= 1) {
            ts  += __shfl_xor_sync(0xffffffffu, ts, off);
            ts2 += __shfl_xor_sync(0xffffffffu, ts2, off);
        }
        if (tid == 0) {
            const float inv = 1.0f / (16.0f * HWc);
            float mu  = ts * inv;
            float var = ts2 * inv - mu * mu;
            mean_s = mu;
            rstd_s = rsqrtf(var + 1e-5f);
        }
    }
    __syncthreads();
    if (tid < 16) {
        int c = g * 16 + tid;
        float sc = rstd_s * gamma[c];
        ss[(b * Cn + c) * 2 + 0] = sc;
        ss[(b * Cn + c) * 2 + 1] = beta[c] - mean_s * sc;
    }
}

// ---------------- horizontal scans: warp-per-row parallel scan ----------------
__global__ __launch_bounds__(256) void scan_w_kernel(const float* __restrict__ ap,
                                                     const float* __restrict__ bp,
                                                     const float* __restrict__ cp,
                                                     const float* __restrict__ dp)
{
    const int gw = blockIdx.x * 8 + (threadIdx.x >> 5);
    const int lane = threadIdx.x & 31;
    const int bc = gw / Hn;
    const int c  = bc & (Cn - 1);
    const float2 sc = *(const float2*)&g_ss1[bc * 2];
    const float a0 = sigmoid_f(ap[c]),    b0 = bp[c],    c0 = cp[c],    d0 = dp[c];
    const float a1 = sigmoid_f(ap[Cn+c]), b1 = bp[Cn+c], c1 = cp[Cn+c], d1 = dp[Cn+c];
    const float* xr = g_xp + (size_t)gw * Wn;

    float x0 = 0.f, x1 = 0.f, x2 = 0.f, x3 = 0.f;
    if (lane < 24) {
        float4 v = *(const float4*)(xr + lane * 4);
        x0 = silu_f(fmaf(v.x, sc.x, sc.y));
        x1 = silu_f(fmaf(v.y, sc.x, sc.y));
        x2 = silu_f(fmaf(v.z, sc.x, sc.y));
        x3 = silu_f(fmaf(v.w, sc.x, sc.y));
    }
    float a0_4 = (a0 * a0) * (a0 * a0);
    float S = b0 * x0;
    S = fmaf(a0, S, b0 * x1); S = fmaf(a0, S, b0 * x2); S = fmaf(a0, S, b0 * x3);
    float P = a0_4;
#pragma unroll
    for (int off = 1; off < 32; off <<= 1) {
        float Sp = __shfl_up_sync(0xffffffffu, S, off);
        float Pp = __shfl_up_sync(0xffffffffu, P, off);
        if (lane >= off) { S = fmaf(Sp, P, S); P *= Pp; }
    }
    float Hin = __shfl_up_sync(0xffffffffu, S, 1);
    if (lane == 0) Hin = 0.f;
    float hh = Hin;
    hh = fmaf(a0, hh, b0 * x0); float y0 = fmaf(c0, hh, d0 * x0);
    hh = fmaf(a0, hh, b0 * x1); float y1 = fmaf(c0, hh, d0 * x1);
    hh = fmaf(a0, hh, b0 * x2); float y2 = fmaf(c0, hh, d0 * x2);
    hh = fmaf(a0, hh, b0 * x3); float y3 = fmaf(c0, hh, d0 * x3);
    float a1_4 = (a1 * a1) * (a1 * a1);
    float S2 = b1 * x3;
    S2 = fmaf(a1, S2, b1 * x2); S2 = fmaf(a1, S2, b1 * x1); S2 = fmaf(a1, S2, b1 * x0);
    float P2 = a1_4;
    if (lane >= 24) { S2 = 0.f; P2 = 1.f; }
#pragma unroll
    for (int off = 1; off < 32; off <<= 1) {
        float Sp = __shfl_down_sync(0xffffffffu, S2, off);
        float Pp = __shfl_down_sync(0xffffffffu, P2, off);
        if (lane + off < 32) { S2 = fmaf(Sp, P2, S2); P2 *= Pp; }
    }
    float Hin2 = __shfl_down_sync(0xffffffffu, S2, 1);
    if (lane == 31) Hin2 = 0.f;
    hh = Hin2;
    hh = fmaf(a1, hh, b1 * x3); y3 += fmaf(c1, hh, d1 * x3);
    hh = fmaf(a1, hh, b1 * x2); y2 += fmaf(c1, hh, d1 * x2);
    hh = fmaf(a1, hh, b1 * x1); y1 += fmaf(c1, hh, d1 * x1);
    hh = fmaf(a1, hh, b1 * x0); y0 += fmaf(c1, hh, d1 * x0);

    if (lane < 24)
        *(float4*)(g_sw + (size_t)gw * Wn + lane * 4) = make_float4(y0, y1, y2, y3);
}

// ---------------- vertical scans: block per (b,c), thread per column ----------------
__global__ __launch_bounds__(96) void scan_h_kernel(const float* __restrict__ ap,
                                                    const float* __restrict__ bp,
                                                    const float* __restrict__ cp,
                                                    const float* __restrict__ dp)
{
    __shared__ float ytmp[HWc];   // 36 KB
    const int bc = blockIdx.x;
    const int c  = bc & (Cn - 1);
    const int tid = threadIdx.x;
    const float2 sc = *(const float2*)&g_ss1[bc * 2];
    const size_t base = (size_t)bc * HWc;

    const float a2 = sigmoid_f(ap[2*Cn+c]), b2 = bp[2*Cn+c], c2 = cp[2*Cn+c], d2 = dp[2*Cn+c];
    const float a3 = sigmoid_f(ap[3*Cn+c]), b3 = bp[3*Cn+c], c3 = cp[3*Cn+c], d3 = dp[3*Cn+c];
    const int w = tid;
    float hs = 0.f;
#pragma unroll 4
    for (int hhi = Hn - 1; hhi >= 0; hhi--) {
        float xv = silu_f(fmaf(g_xp[base + hhi * Wn + w], sc.x, sc.y));
        hs = fmaf(a3, hs, b3 * xv);
        ytmp[hhi * Wn + w] = fmaf(c3, hs, d3 * xv);
    }
    hs = 0.f;
#pragma unroll 4
    for (int hhi = 0; hhi < Hn; hhi++) {
        float xv = silu_f(fmaf(g_xp[base + hhi * Wn + w], sc.x, sc.y));
        hs = fmaf(a2, hs, b2 * xv);
        g_sh[base + hhi * Wn + w] = fmaf(c2, hs, d2 * xv) + ytmp[hhi * Wn + w];
    }
}

// ---------------- fused = 0.25*(sw+sh)*gate, 3x3 depthwise SAME conv ----------------
__global__ __launch_bounds__(256) void fuse_dw_kernel(const float* __restrict__ dww)
{
    __shared__ float ft[34 * 36];
    const int bc = blockIdx.z;
    const int h0 = blockIdx.y * 32, w0 = blockIdx.x * 32;
    const int c = bc & (Cn - 1);
    const size_t base = (size_t)bc * HWc;
    const int tid = threadIdx.x;

    for (int i = tid; i < 34 * 34; i += 256) {
        int r = i / 34, cc = i - r * 34;
        int gh = h0 - 1 + r, gw = w0 - 1 + cc;
        float v = 0.0f;
        if ((unsigned)gh < (unsigned)Hn && (unsigned)gw < (unsigned)Wn) {
            size_t idx = base + gh * Wn + gw;
            v = 0.25f * (g_sw[idx] + g_sh[idx]) * g_gate[idx];
        }
        ft[r * 36 + cc] = v;
    }
    float kw[9];
#pragma unroll
    for (int j = 0; j < 9; j++) kw[j] = dww[c * 9 + j];
    __syncthreads();

    const int tx = tid & 31, ty0 = tid >> 5;
#pragma unroll
    for (int rr = 0; rr < 4; rr++) {
        int r = ty0 + rr * 8;
        float acc = 0.0f;
#pragma unroll
        for (int i = 0; i < 3; i++)
#pragma unroll
            for (int j = 0; j < 3; j++)
                acc = fmaf(ft[(r + i) * 36 + tx + j], kw[i * 3 + j], acc);
        g_fd[base + (size_t)(h0 + r) * Wn + w0 + tx] = acc;
    }
}

// ---------------- final: silu(affine(o1)) -> out ----------------
__global__ __launch_bounds__(256) void finalize_kernel(const float* __restrict__ src,
                                                       const float* __restrict__ ss,
                                                       float* __restrict__ out)
{
    int i4 = blockIdx.x * 256 + threadIdx.x;
    if (i4 >= TOTc / 4) return;
    int bc = i4 / (HWc / 4);
    float2 sc = *(const float2*)&ss[bc * 2];
    float4 v = ((const float4*)src)[i4];
    v.x = silu_f(fmaf(v.x, sc.x, sc.y));
    v.y = silu_f(fmaf(v.y, sc.x, sc.y));
    v.z = silu_f(fmaf(v.z, sc.x, sc.y));
    v.w = silu_f(fmaf(v.w, sc.x, sc.y));
    ((float4*)out)[i4] = v;
}

// ---------------- launch ----------------
extern "C" void kernel_launch(void* const* d_in, const int* in_sizes, int n_in,
                              void* d_out, int out_size)
{
    const float* x      = (const float*)d_in[0];
    const float* in_w   = (const float*)d_in[1];
    const float* gn1_w  = (const float*)d_in[2];
    const float* gn1_b  = (const float*)d_in[3];
    const float* a_p    = (const float*)d_in[4];
    const float* b_p    = (const float*)d_in[5];
    const float* c_p    = (const float*)d_in[6];
    const float* d_p    = (const float*)d_in[7];
    const float* gate_w = (const float*)d_in[8];
    const float* gate_b = (const float*)d_in[9];
    const float* dw_w   = (const float*)d_in[10];
    const float* pw_w   = (const float*)d_in[11];
    const float* gn2_w  = (const float*)d_in[12];
    const float* gn2_b  = (const float*)d_in[13];
    float* out = (float*)d_out;

    float *p_xp, *p_gate, *p_fd, *p_o1, *p_ss1, *p_ss2;
    __nv_bfloat16 *p_bth, *p_btl, *p_ah, *p_al;
    cudaGetSymbolAddress((void**)&p_xp,   g_xp);
    cudaGetSymbolAddress((void**)&p_gate, g_gate);
    cudaGetSymbolAddress((void**)&p_fd,   g_fd);
    cudaGetSymbolAddress((void**)&p_o1,   g_o1);
    cudaGetSymbolAddress((void**)&p_ss1,  g_ss1);
    cudaGetSymbolAddress((void**)&p_ss2,  g_ss2);
    cudaGetSymbolAddress((void**)&p_bth,  g_bth);
    cudaGetSymbolAddress((void**)&p_btl,  g_btl);
    cudaGetSymbolAddress((void**)&p_ah,   g_ahh);
    cudaGetSymbolAddress((void**)&p_al,   g_all);

    cudaFuncSetAttribute(gemm_mma_kernel, cudaFuncAttributeMaxDynamicSharedMemorySize, GSM_TOT);

    dim3 gcv(HWc / 32, Cn / 32, Bn);
    dim3 bcv(32, 8);
    dim3 gmm(HWc / 128, Cn / 128, Bn);

    // convert all three weight matrices up front
    convA3_kernel<<<3 * Cn * Cn / 256, 256>>>(in_w, gate_w, pw_w, p_ah, p_al);

    // GEMM1: xp = in_w @ x
    convT_kernel<<<gcv, bcv>>>(x, p_bth, p_btl, p_ss1, 0);
    gemm_mma_kernel<<<gmm, 512, GSM_TOT>>>(p_ah, p_al, p_bth, p_btl, p_xp, gate_b, 0);
    gn_stats_kernel<<<dim3(16, Bn), 1024>>>(p_xp, gn1_w, gn1_b, p_ss1);

    // gate GEMM: gate = sigmoid(gate_w @ silu(affine(xp)) + b)
    convT_kernel<<<gcv, bcv>>>(p_xp, p_bth, p_btl, p_ss1, 1);
    gemm_mma_kernel<<<gmm, 512, GSM_TOT>>>(p_ah + 65536, p_al + 65536, p_bth, p_btl, p_gate, gate_b, 1);

    // scans + fuse + depthwise
    scan_w_kernel<<<Bn * Cn * Hn / 8, 256>>>(a_p, b_p, c_p, d_p);
    scan_h_kernel<<<Bn * Cn, 96>>>(a_p, b_p, c_p, d_p);
    fuse_dw_kernel<<<dim3(3, 3, Bn * Cn), 256>>>(dw_w);

    // GEMM3: o1 = pw_w @ fd
    convT_kernel<<<gcv, bcv>>>(p_fd, p_bth, p_btl, p_ss1, 0);
    gemm_mma_kernel<<<gmm, 512, GSM_TOT>>>(p_ah + 131072, p_al + 131072, p_bth, p_btl, p_o1, gate_b, 0);

    gn_stats_kernel<<<dim3(16, Bn), 1024>>>(p_o1, gn2_w, gn2_b, p_ss2);
    finalize_kernel<<<(TOTc / 4 + 255) / 256, 256>>>(p_o1, p_ss2, out);
}

// round 14
// speedup vs baseline: 1.3881x; 1.3881x over previous
#include <cuda_runtime.h>
#include <cuda_bf16.h>
#include <cstdint>

#define Bn 16
#define Cn 256
#define Hn 96
#define Wn 96
#define HWc 9216
#define CHWc 2359296   // Cn*HWc
#define TOTc 37748736  // Bn*CHWc

// ---------------- scratch ----------------
__device__ float g_xp[TOTc];
__device__ float g_gate[TOTc];
__device__ float g_sw[TOTc];
__device__ float g_sh[TOTc];
__device__ float g_fd[TOTc];
__device__ float g_o1[TOTc];
__device__ float g_ss1[Bn*Cn*2];
__device__ float g_ss2[Bn*Cn*2];
__device__ __nv_bfloat16 g_bth[TOTc];       // B transposed [b][n][k], hi
__device__ __nv_bfloat16 g_btl[TOTc];       // lo
__device__ __nv_bfloat16 g_ahh[3*Cn*Cn];    // A hi (in_w, gate_w, pw_w)
__device__ __nv_bfloat16 g_all[3*Cn*Cn];    // A lo

__device__ __forceinline__ float sigmoid_f(float x) { return 1.0f / (1.0f + __expf(-x)); }
__device__ __forceinline__ float silu_f(float x)    { return x / (1.0f + __expf(-x)); }

__device__ __forceinline__ uint32_t smem_u32(const void* p) {
    uint32_t a;
    asm("{ .reg .u64 t; cvta.to.shared.u64 t, %1; cvt.u32.u64 %0, t; }" : "=r"(a) : "l"(p));
    return a;
}
__device__ __forceinline__ void ldsm4(uint32_t &r0, uint32_t &r1, uint32_t &r2, uint32_t &r3, uint32_t addr) {
    asm volatile("ldmatrix.sync.aligned.m8n8.x4.shared.b16 {%0,%1,%2,%3}, [%4];"
                 : "=r"(r0), "=r"(r1), "=r"(r2), "=r"(r3) : "r"(addr));
}
__device__ __forceinline__ void mma16816(float* d, const uint32_t* a, const uint32_t* b) {
    asm volatile("mma.sync.aligned.m16n8k16.row.col.f32.bf16.bf16.f32 "
                 "{%0,%1,%2,%3}, {%4,%5,%6,%7}, {%8,%9}, {%0,%1,%2,%3};"
                 : "+f"(d[0]), "+f"(d[1]), "+f"(d[2]), "+f"(d[3])
                 : "r"(a[0]), "r"(a[1]), "r"(a[2]), "r"(a[3]), "r"(b[0]), "r"(b[1]));
}
__device__ __forceinline__ void cpa16(uint32_t sm, const void* g) {
    asm volatile("cp.async.cg.shared.global [%0], [%1], 16;" :: "r"(sm), "l"(g));
}
#define CPA_COMMIT() asm volatile("cp.async.commit_group;" ::: "memory")
#define CPA_WAIT1()  asm volatile("cp.async.wait_group 1;" ::: "memory")
#define CPA_WAIT0()  asm volatile("cp.async.wait_group 0;" ::: "memory")

// ================ conversion kernels ================
__global__ __launch_bounds__(256) void convA3_kernel(const float* __restrict__ w0,
                                                     const float* __restrict__ w1,
                                                     const float* __restrict__ w2,
                                                     __nv_bfloat16* __restrict__ ah,
                                                     __nv_bfloat16* __restrict__ al)
{
    int i = blockIdx.x * 256 + threadIdx.x;
    int which = i >> 16, j = i & 65535;
    const float* s = (which == 0) ? w0 : ((which == 1) ? w1 : w2);
    float v = s[j];
    __nv_bfloat16 h = __float2bfloat16(v);
    ah[i] = h;
    al[i] = __float2bfloat16(v - __bfloat162float(h));
}

// src fp32 [b][K=256][N=9216] -> bh/bl bf16 [b][N=9216][K=256]; mode1: silu(affine) via ss
__global__ __launch_bounds__(256) void convT_kernel(const float* __restrict__ src,
                                                    __nv_bfloat16* __restrict__ bh,
                                                    __nv_bfloat16* __restrict__ bl,
                                                    const float* __restrict__ ss, int mode)
{
    __shared__ float t[32][33];
    const int n0 = blockIdx.x * 32, k0 = blockIdx.y * 32, bb = blockIdx.z;
    const int tx = threadIdx.x, ty = threadIdx.y;
#pragma unroll
    for (int i = 0; i < 4; i++) {
        int k = k0 + ty + 8 * i;
        float v = src[(size_t)bb * CHWc + (size_t)k * HWc + n0 + tx];
        if (mode) {
            float2 sc = *(const float2*)&ss[(bb * Cn + k) * 2];
            v = silu_f(fmaf(v, sc.x, sc.y));
        }
        t[ty + 8 * i][tx] = v;
    }
    __syncthreads();
#pragma unroll
    for (int i = 0; i < 4; i++) {
        int n = n0 + ty + 8 * i;
        float v = t[tx][ty + 8 * i];
        __nv_bfloat16 h = __float2bfloat16(v);
        size_t o = (size_t)bb * CHWc + (size_t)n * Cn + k0 + tx;
        bh[o] = h;
        bl[o] = __float2bfloat16(v - __bfloat162float(h));
    }
}

// ================ k-folded bf16 warp-MMA GEMM (round-12 structure + ldsm4-B) ========
// C[b][m][n] = sum_k A[m][k]*Bt[b][n][k]. BM=128, BN=128, BK=32.
// 512 threads = 16 warps (4m x 4n), warp tile 32x32. 8 k-iters; per fragment load,
// 3 products (Ah*Bh, Al*Bh, Ah*Bl). 2-stage cp.async (80KB smem: stays under the
// 2-CTA/SM smem cliff discovered in round 13).
#define PITCH 40                 // bf16/row: 80B stride, conflict-free ldmatrix
#define TILE_B (128 * PITCH * 2) // 10240 bytes per (array, stage)
#define OFF_AH 0
#define OFF_AL TILE_B
#define OFF_BH (2*TILE_B)
#define OFF_BL (3*TILE_B)
#define STG (4*TILE_B)           // 40960
#define GSM_TOT (2*STG)          // 81920

__global__ __launch_bounds__(512) void gemm_mma_kernel(
    const __nv_bfloat16* __restrict__ Ah, const __nv_bfloat16* __restrict__ Al,
    const __nv_bfloat16* __restrict__ Bh, const __nv_bfloat16* __restrict__ Bl,
    float* __restrict__ Cd, const float* __restrict__ gbias, int mode)
{
    extern __shared__ __align__(16) char gsm[];
    const uint32_t su = smem_u32(gsm);
    const int tid = threadIdx.x, lane = tid & 31, warp = tid >> 5;
    const int wm = (warp & 3) * 32, wn = (warp >> 2) * 32;
    const int n0 = blockIdx.x * 128, bm = blockIdx.y * 128, bb = blockIdx.z;

    // staging: thread t -> row = t>>2 (0..127), 16B chunk = t&3
    const int s_r = tid >> 2, s_c = (tid & 3);
    const uint32_t s_off = (uint32_t)(s_r * (PITCH * 2) + s_c * 16);
    const size_t a_go = (size_t)(bm + s_r) * 256 + s_c * 8;
    const size_t b_go = ((size_t)bb * HWc + n0 + s_r) * 256 + s_c * 8;

    float acc[2][4][4];
#pragma unroll
    for (int i = 0; i < 2; i++)
#pragma unroll
        for (int j = 0; j < 4; j++)
#pragma unroll
            for (int k = 0; k < 4; k++) acc[i][j][k] = 0.0f;

    // prologue: stages 0 and 1
#pragma unroll
    for (int pre = 0; pre < 2; pre++) {
        const uint32_t sb = su + pre * STG;
        const int k0 = pre * 32;
        cpa16(sb + OFF_AH + s_off, Ah + a_go + k0);
        cpa16(sb + OFF_AL + s_off, Al + a_go + k0);
        cpa16(sb + OFF_BH + s_off, Bh + b_go + k0);
        cpa16(sb + OFF_BL + s_off, Bl + b_go + k0);
        CPA_COMMIT();
    }

    for (int it = 0; it < 8; it++) {
        if (it < 7) CPA_WAIT1(); else CPA_WAIT0();
        __syncthreads();
        const uint32_t sb = su + (it & 1) * STG;
#pragma unroll
        for (int ks = 0; ks < 2; ks++) {
            uint32_t ahf[2][4], alf[2][4], bhf[4][2], blf[4][2];
#pragma unroll
            for (int mt = 0; mt < 2; mt++) {
                uint32_t ao = (uint32_t)(((wm + mt * 16 + (lane & 15)) * PITCH
                                          + ks * 16 + (lane >> 4) * 8) << 1);
                ldsm4(ahf[mt][0], ahf[mt][1], ahf[mt][2], ahf[mt][3], sb + OFF_AH + ao);
                ldsm4(alf[mt][0], alf[mt][1], alf[mt][2], alf[mt][3], sb + OFF_AL + ao);
            }
            // B: one ldsm4 covers two n-tiles (lane bit4 -> +8 rows, bit3 -> +8 cols)
#pragma unroll
            for (int ntp = 0; ntp < 2; ntp++) {
                uint32_t bo = (uint32_t)(((wn + ntp * 16 + ((lane >> 4) & 1) * 8 + (lane & 7)) * PITCH
                                          + ks * 16 + ((lane >> 3) & 1) * 8) << 1);
                ldsm4(bhf[2*ntp][0], bhf[2*ntp][1], bhf[2*ntp+1][0], bhf[2*ntp+1][1], sb + OFF_BH + bo);
                ldsm4(blf[2*ntp][0], blf[2*ntp][1], blf[2*ntp+1][0], blf[2*ntp+1][1], sb + OFF_BL + bo);
            }
#pragma unroll
            for (int mt = 0; mt < 2; mt++)
#pragma unroll
                for (int nt = 0; nt < 4; nt++) {
                    mma16816(acc[mt][nt], ahf[mt], bhf[nt]);
                    mma16816(acc[mt][nt], alf[mt], bhf[nt]);
                    mma16816(acc[mt][nt], ahf[mt], blf[nt]);
                }
        }
        if (it < 6) {
            __syncthreads();
            const int k0 = (it + 2) * 32;
            cpa16(sb + OFF_AH + s_off, Ah + a_go + k0);
            cpa16(sb + OFF_AL + s_off, Al + a_go + k0);
            cpa16(sb + OFF_BH + s_off, Bh + b_go + k0);
            cpa16(sb + OFF_BL + s_off, Bl + b_go + k0);
            CPA_COMMIT();
        }
    }

    // epilogue: fragment rows lane/4 (+8), cols 2*(lane%4)+{0,1}
    const int gr = lane >> 2, gc = (lane & 3) * 2;
#pragma unroll
    for (int mt = 0; mt < 2; mt++) {
        const int row0 = bm + wm + mt * 16 + gr;
        float* p0 = Cd + (size_t)bb * CHWc + (size_t)row0 * HWc + n0 + wn;
        float* p1 = p0 + (size_t)8 * HWc;
        if (mode == 0) {
#pragma unroll
            for (int nt = 0; nt < 4; nt++) {
                *(float2*)(p0 + nt * 8 + gc) = make_float2(acc[mt][nt][0], acc[mt][nt][1]);
                *(float2*)(p1 + nt * 8 + gc) = make_float2(acc[mt][nt][2], acc[mt][nt][3]);
            }
        } else {
            const float gb0 = gbias[row0], gb1 = gbias[row0 + 8];
#pragma unroll
            for (int nt = 0; nt < 4; nt++) {
                *(float2*)(p0 + nt * 8 + gc) =
                    make_float2(sigmoid_f(acc[mt][nt][0] + gb0), sigmoid_f(acc[mt][nt][1] + gb0));
                *(float2*)(p1 + nt * 8 + gc) =
                    make_float2(sigmoid_f(acc[mt][nt][2] + gb1), sigmoid_f(acc[mt][nt][3] + gb1));
            }
        }
    }
}

// ---------------- GroupNorm stats -> per-(b,c) affine ----------------
__global__ __launch_bounds__(1024) void gn_stats_kernel(const float* __restrict__ src,
                                                        const float* __restrict__ gamma,
                                                        const float* __restrict__ beta,
                                                        float* __restrict__ ss)
{
    const int g = blockIdx.x, b = blockIdx.y, tid = threadIdx.x;
    const float4* p = (const float4*)(src + (size_t)b * CHWc + (size_t)g * 16 * HWc);
    float s = 0.0f, s2 = 0.0f;
    const int n4 = 16 * HWc / 4;
    for (int i = tid; i < n4; i += 1024) {
        float4 v = p[i];
        s  += v.x + v.y + v.z + v.w;
        s2 += v.x * v.x + v.y * v.y + v.z * v.z + v.w * v.w;
    }
#pragma unroll
    for (int off = 16; off > 0; off >>= 1) {
        s  += __shfl_xor_sync(0xffffffffu, s, off);
        s2 += __shfl_xor_sync(0xffffffffu, s2, off);
    }
    __shared__ float ws[32], ws2[32];
    __shared__ float mean_s, rstd_s;
    const int wid = tid >> 5, lane = tid & 31;
    if (lane == 0) { ws[wid] = s; ws2[wid] = s2; }
    __syncthreads();
    if (tid < 32) {
        float ts = ws[tid], ts2 = ws2[tid];
#pragma unroll
        for (int off = 16; off > 0; off >>= 1) {
            ts  += __shfl_xor_sync(0xffffffffu, ts, off);
            ts2 += __shfl_xor_sync(0xffffffffu, ts2, off);
        }
        if (tid == 0) {
            const float inv = 1.0f / (16.0f * HWc);
            float mu  = ts * inv;
            float var = ts2 * inv - mu * mu;
            mean_s = mu;
            rstd_s = rsqrtf(var + 1e-5f);
        }
    }
    __syncthreads();
    if (tid < 16) {
        int c = g * 16 + tid;
        float sc = rstd_s * gamma[c];
        ss[(b * Cn + c) * 2 + 0] = sc;
        ss[(b * Cn + c) * 2 + 1] = beta[c] - mean_s * sc;
    }
}

// ---------------- horizontal scans: warp-per-row parallel scan ----------------
__global__ __launch_bounds__(256) void scan_w_kernel(const float* __restrict__ ap,
                                                     const float* __restrict__ bp,
                                                     const float* __restrict__ cp,
                                                     const float* __restrict__ dp)
{
    const int gw = blockIdx.x * 8 + (threadIdx.x >> 5);
    const int lane = threadIdx.x & 31;
    const int bc = gw / Hn;
    const int c  = bc & (Cn - 1);
    const float2 sc = *(const float2*)&g_ss1[bc * 2];
    const float a0 = sigmoid_f(ap[c]),    b0 = bp[c],    c0 = cp[c],    d0 = dp[c];
    const float a1 = sigmoid_f(ap[Cn+c]), b1 = bp[Cn+c], c1 = cp[Cn+c], d1 = dp[Cn+c];
    const float* xr = g_xp + (size_t)gw * Wn;

    float x0 = 0.f, x1 = 0.f, x2 = 0.f, x3 = 0.f;
    if (lane < 24) {
        float4 v = *(const float4*)(xr + lane * 4);
        x0 = silu_f(fmaf(v.x, sc.x, sc.y));
        x1 = silu_f(fmaf(v.y, sc.x, sc.y));
        x2 = silu_f(fmaf(v.z, sc.x, sc.y));
        x3 = silu_f(fmaf(v.w, sc.x, sc.y));
    }
    float a0_4 = (a0 * a0) * (a0 * a0);
    float S = b0 * x0;
    S = fmaf(a0, S, b0 * x1); S = fmaf(a0, S, b0 * x2); S = fmaf(a0, S, b0 * x3);
    float P = a0_4;
#pragma unroll
    for (int off = 1; off < 32; off <<= 1) {
        float Sp = __shfl_up_sync(0xffffffffu, S, off);
        float Pp = __shfl_up_sync(0xffffffffu, P, off);
        if (lane >= off) { S = fmaf(Sp, P, S); P *= Pp; }
    }
    float Hin = __shfl_up_sync(0xffffffffu, S, 1);
    if (lane == 0) Hin = 0.f;
    float hh = Hin;
    hh = fmaf(a0, hh, b0 * x0); float y0 = fmaf(c0, hh, d0 * x0);
    hh = fmaf(a0, hh, b0 * x1); float y1 = fmaf(c0, hh, d0 * x1);
    hh = fmaf(a0, hh, b0 * x2); float y2 = fmaf(c0, hh, d0 * x2);
    hh = fmaf(a0, hh, b0 * x3); float y3 = fmaf(c0, hh, d0 * x3);
    float a1_4 = (a1 * a1) * (a1 * a1);
    float S2 = b1 * x3;
    S2 = fmaf(a1, S2, b1 * x2); S2 = fmaf(a1, S2, b1 * x1); S2 = fmaf(a1, S2, b1 * x0);
    float P2 = a1_4;
    if (lane >= 24) { S2 = 0.f; P2 = 1.f; }
#pragma unroll
    for (int off = 1; off < 32; off <<= 1) {
        float Sp = __shfl_down_sync(0xffffffffu, S2, off);
        float Pp = __shfl_down_sync(0xffffffffu, P2, off);
        if (lane + off < 32) { S2 = fmaf(Sp, P2, S2); P2 *= Pp; }
    }
    float Hin2 = __shfl_down_sync(0xffffffffu, S2, 1);
    if (lane == 31) Hin2 = 0.f;
    hh = Hin2;
    hh = fmaf(a1, hh, b1 * x3); y3 += fmaf(c1, hh, d1 * x3);
    hh = fmaf(a1, hh, b1 * x2); y2 += fmaf(c1, hh, d1 * x2);
    hh = fmaf(a1, hh, b1 * x1); y1 += fmaf(c1, hh, d1 * x1);
    hh = fmaf(a1, hh, b1 * x0); y0 += fmaf(c1, hh, d1 * x0);

    if (lane < 24)
        *(float4*)(g_sw + (size_t)gw * Wn + lane * 4) = make_float4(y0, y1, y2, y3);
}

// ---------------- vertical scans: block per (b,c), thread per column ----------------
__global__ __launch_bounds__(96) void scan_h_kernel(const float* __restrict__ ap,
                                                    const float* __restrict__ bp,
                                                    const float* __restrict__ cp,
                                                    const float* __restrict__ dp)
{
    __shared__ float ytmp[HWc];   // 36 KB
    const int bc = blockIdx.x;
    const int c  = bc & (Cn - 1);
    const int tid = threadIdx.x;
    const float2 sc = *(const float2*)&g_ss1[bc * 2];
    const size_t base = (size_t)bc * HWc;

    const float a2 = sigmoid_f(ap[2*Cn+c]), b2 = bp[2*Cn+c], c2 = cp[2*Cn+c], d2 = dp[2*Cn+c];
    const float a3 = sigmoid_f(ap[3*Cn+c]), b3 = bp[3*Cn+c], c3 = cp[3*Cn+c], d3 = dp[3*Cn+c];
    const int w = tid;
    float hs = 0.f;
#pragma unroll 4
    for (int hhi = Hn - 1; hhi >= 0; hhi--) {
        float xv = silu_f(fmaf(g_xp[base + hhi * Wn + w], sc.x, sc.y));
        hs = fmaf(a3, hs, b3 * xv);
        ytmp[hhi * Wn + w] = fmaf(c3, hs, d3 * xv);
    }
    hs = 0.f;
#pragma unroll 4
    for (int hhi = 0; hhi < Hn; hhi++) {
        float xv = silu_f(fmaf(g_xp[base + hhi * Wn + w], sc.x, sc.y));
        hs = fmaf(a2, hs, b2 * xv);
        g_sh[base + hhi * Wn + w] = fmaf(c2, hs, d2 * xv) + ytmp[hhi * Wn + w];
    }
}

// ---------------- fused = 0.25*(sw+sh)*gate, 3x3 depthwise SAME conv ----------------
__global__ __launch_bounds__(256) void fuse_dw_kernel(const float* __restrict__ dww)
{
    __shared__ float ft[34 * 36];
    const int bc = blockIdx.z;
    const int h0 = blockIdx.y * 32, w0 = blockIdx.x * 32;
    const int c = bc & (Cn - 1);
    const size_t base = (size_t)bc * HWc;
    const int tid = threadIdx.x;

    for (int i = tid; i < 34 * 34; i += 256) {
        int r = i / 34, cc = i - r * 34;
        int gh = h0 - 1 + r, gw = w0 - 1 + cc;
        float v = 0.0f;
        if ((unsigned)gh < (unsigned)Hn && (unsigned)gw < (unsigned)Wn) {
            size_t idx = base + gh * Wn + gw;
            v = 0.25f * (g_sw[idx] + g_sh[idx]) * g_gate[idx];
        }
        ft[r * 36 + cc] = v;
    }
    float kw[9];
#pragma unroll
    for (int j = 0; j < 9; j++) kw[j] = dww[c * 9 + j];
    __syncthreads();

    const int tx = tid & 31, ty0 = tid >> 5;
#pragma unroll
    for (int rr = 0; rr < 4; rr++) {
        int r = ty0 + rr * 8;
        float acc = 0.0f;
#pragma unroll
        for (int i = 0; i < 3; i++)
#pragma unroll
            for (int j = 0; j < 3; j++)
                acc = fmaf(ft[(r + i) * 36 + tx + j], kw[i * 3 + j], acc);
        g_fd[base + (size_t)(h0 + r) * Wn + w0 + tx] = acc;
    }
}

// ---------------- final: silu(affine(o1)) -> out ----------------
__global__ __launch_bounds__(256) void finalize_kernel(const float* __restrict__ src,
                                                       const float* __restrict__ ss,
                                                       float* __restrict__ out)
{
    int i4 = blockIdx.x * 256 + threadIdx.x;
    if (i4 >= TOTc / 4) return;
    int bc = i4 / (HWc / 4);
    float2 sc = *(const float2*)&ss[bc * 2];
    float4 v = ((const float4*)src)[i4];
    v.x = silu_f(fmaf(v.x, sc.x, sc.y));
    v.y = silu_f(fmaf(v.y, sc.x, sc.y));
    v.z = silu_f(fmaf(v.z, sc.x, sc.y));
    v.w = silu_f(fmaf(v.w, sc.x, sc.y));
    ((float4*)out)[i4] = v;
}

// ---------------- launch ----------------
extern "C" void kernel_launch(void* const* d_in, const int* in_sizes, int n_in,
                              void* d_out, int out_size)
{
    const float* x      = (const float*)d_in[0];
    const float* in_w   = (const float*)d_in[1];
    const float* gn1_w  = (const float*)d_in[2];
    const float* gn1_b  = (const float*)d_in[3];
    const float* a_p    = (const float*)d_in[4];
    const float* b_p    = (const float*)d_in[5];
    const float* c_p    = (const float*)d_in[6];
    const float* d_p    = (const float*)d_in[7];
    const float* gate_w = (const float*)d_in[8];
    const float* gate_b = (const float*)d_in[9];
    const float* dw_w   = (const float*)d_in[10];
    const float* pw_w   = (const float*)d_in[11];
    const float* gn2_w  = (const float*)d_in[12];
    const float* gn2_b  = (const float*)d_in[13];
    float* out = (float*)d_out;

    float *p_xp, *p_gate, *p_fd, *p_o1, *p_ss1, *p_ss2;
    __nv_bfloat16 *p_bth, *p_btl, *p_ah, *p_al;
    cudaGetSymbolAddress((void**)&p_xp,   g_xp);
    cudaGetSymbolAddress((void**)&p_gate, g_gate);
    cudaGetSymbolAddress((void**)&p_fd,   g_fd);
    cudaGetSymbolAddress((void**)&p_o1,   g_o1);
    cudaGetSymbolAddress((void**)&p_ss1,  g_ss1);
    cudaGetSymbolAddress((void**)&p_ss2,  g_ss2);
    cudaGetSymbolAddress((void**)&p_bth,  g_bth);
    cudaGetSymbolAddress((void**)&p_btl,  g_btl);
    cudaGetSymbolAddress((void**)&p_ah,   g_ahh);
    cudaGetSymbolAddress((void**)&p_al,   g_all);

    cudaFuncSetAttribute(gemm_mma_kernel, cudaFuncAttributeMaxDynamicSharedMemorySize, GSM_TOT);

    dim3 gcv(HWc / 32, Cn / 32, Bn);
    dim3 bcv(32, 8);
    dim3 gmm(HWc / 128, Cn / 128, Bn);

    // convert all three weight matrices up front
    convA3_kernel<<<3 * Cn * Cn / 256, 256>>>(in_w, gate_w, pw_w, p_ah, p_al);

    // GEMM1: xp = in_w @ x
    convT_kernel<<<gcv, bcv>>>(x, p_bth, p_btl, p_ss1, 0);
    gemm_mma_kernel<<<gmm, 512, GSM_TOT>>>(p_ah, p_al, p_bth, p_btl, p_xp, gate_b, 0);
    gn_stats_kernel<<<dim3(16, Bn), 1024>>>(p_xp, gn1_w, gn1_b, p_ss1);

    // gate GEMM: gate = sigmoid(gate_w @ silu(affine(xp)) + b)
    convT_kernel<<<gcv, bcv>>>(p_xp, p_bth, p_btl, p_ss1, 1);
    gemm_mma_kernel<<<gmm, 512, GSM_TOT>>>(p_ah + 65536, p_al + 65536, p_bth, p_btl, p_gate, gate_b, 1);

    // scans + fuse + depthwise
    scan_w_kernel<<<Bn * Cn * Hn / 8, 256>>>(a_p, b_p, c_p, d_p);
    scan_h_kernel<<<Bn * Cn, 96>>>(a_p, b_p, c_p, d_p);
    fuse_dw_kernel<<<dim3(3, 3, Bn * Cn), 256>>>(dw_w);

    // GEMM3: o1 = pw_w @ fd
    convT_kernel<<<gcv, bcv>>>(p_fd, p_bth, p_btl, p_ss1, 0);
    gemm_mma_kernel<<<gmm, 512, GSM_TOT>>>(p_ah + 131072, p_al + 131072, p_bth, p_btl, p_o1, gate_b, 0);

    gn_stats_kernel<<<dim3(16, Bn), 1024>>>(p_o1, gn2_w, gn2_b, p_ss2);
    finalize_kernel<<<(TOTc / 4 + 255) / 256, 256>>>(p_o1, p_ss2, out);
}

// round 15
// speedup vs baseline: 1.7400x; 1.2534x over previous
#include <cuda_runtime.h>
#include <cuda_fp16.h>
#include <cstdint>

#define Bn 16
#define Cn 256
#define Hn 96
#define Wn 96
#define HWc 9216
#define CHWc 2359296   // Cn*HWc
#define TOTc 37748736  // Bn*CHWc

// ---------------- scratch ----------------
__device__ float g_xp[TOTc];
__device__ float g_gate[TOTc];
__device__ float g_sw[TOTc];
__device__ float g_sh[TOTc];
__device__ float g_fd[TOTc];
__device__ float g_o1[TOTc];
__device__ float g_ss1[Bn*Cn*2];
__device__ float g_ss2[Bn*Cn*2];
__device__ __half g_bt[TOTc];          // B transposed [b][n][k], fp16
__device__ __half g_ahh[3*Cn*Cn];      // A hi (in_w, gate_w, pw_w), fp16
__device__ __half g_all[3*Cn*Cn];      // A lo = A - hi, fp16

__device__ __forceinline__ float sigmoid_f(float x) { return 1.0f / (1.0f + __expf(-x)); }
__device__ __forceinline__ float silu_f(float x)    { return x / (1.0f + __expf(-x)); }

__device__ __forceinline__ uint32_t smem_u32(const void* p) {
    uint32_t a;
    asm("{ .reg .u64 t; cvta.to.shared.u64 t, %1; cvt.u32.u64 %0, t; }" : "=r"(a) : "l"(p));
    return a;
}
__device__ __forceinline__ void ldsm4(uint32_t &r0, uint32_t &r1, uint32_t &r2, uint32_t &r3, uint32_t addr) {
    asm volatile("ldmatrix.sync.aligned.m8n8.x4.shared.b16 {%0,%1,%2,%3}, [%4];"
                 : "=r"(r0), "=r"(r1), "=r"(r2), "=r"(r3) : "r"(addr));
}
__device__ __forceinline__ void mma16816h(float* d, const uint32_t* a, const uint32_t* b) {
    asm volatile("mma.sync.aligned.m16n8k16.row.col.f32.f16.f16.f32 "
                 "{%0,%1,%2,%3}, {%4,%5,%6,%7}, {%8,%9}, {%0,%1,%2,%3};"
                 : "+f"(d[0]), "+f"(d[1]), "+f"(d[2]), "+f"(d[3])
                 : "r"(a[0]), "r"(a[1]), "r"(a[2]), "r"(a[3]), "r"(b[0]), "r"(b[1]));
}
__device__ __forceinline__ void cpa16(uint32_t sm, const void* g) {
    asm volatile("cp.async.cg.shared.global [%0], [%1], 16;" :: "r"(sm), "l"(g));
}
#define CPA_COMMIT() asm volatile("cp.async.commit_group;" ::: "memory")
#define CPA_WAIT1()  asm volatile("cp.async.wait_group 1;" ::: "memory")
#define CPA_WAIT0()  asm volatile("cp.async.wait_group 0;" ::: "memory")

// ================ conversion kernels ================
__global__ __launch_bounds__(256) void convA3_kernel(const float* __restrict__ w0,
                                                     const float* __restrict__ w1,
                                                     const float* __restrict__ w2,
                                                     __half* __restrict__ ah,
                                                     __half* __restrict__ al)
{
    int i = blockIdx.x * 256 + threadIdx.x;
    int which = i >> 16, j = i & 65535;
    const float* s = (which == 0) ? w0 : ((which == 1) ? w1 : w2);
    float v = s[j];
    __half h = __float2half(v);
    ah[i] = h;
    al[i] = __float2half(v - __half2float(h));
}

// src fp32 [b][K=256][N=9216] -> fp16 [b][N=9216][K=256]; mode1: silu(affine) via ss
__global__ __launch_bounds__(256) void convT_kernel(const float* __restrict__ src,
                                                    __half* __restrict__ bh,
                                                    const float* __restrict__ ss, int mode)
{
    __shared__ float t[32][33];
    const int n0 = blockIdx.x * 32, k0 = blockIdx.y * 32, bb = blockIdx.z;
    const int tx = threadIdx.x, ty = threadIdx.y;
#pragma unroll
    for (int i = 0; i < 4; i++) {
        int k = k0 + ty + 8 * i;
        float v = src[(size_t)bb * CHWc + (size_t)k * HWc + n0 + tx];
        if (mode) {
            float2 sc = *(const float2*)&ss[(bb * Cn + k) * 2];
            v = silu_f(fmaf(v, sc.x, sc.y));
        }
        t[ty + 8 * i][tx] = v;
    }
    __syncthreads();
#pragma unroll
    for (int i = 0; i < 4; i++) {
        int n = n0 + ty + 8 * i;
        bh[(size_t)bb * CHWc + (size_t)n * Cn + k0 + tx] = __float2half(t[tx][ty + 8 * i]);
    }
}

// ================ 2-pass fp16 warp-MMA GEMM ================
// C[b][m][n] = sum_k A[m][k]*Bt[b][n][k]. BM=128, BN=128, BK=32.
// 512 threads = 16 warps (4m x 4n), warp tile 32x32. 8 k-iters; per fragment load,
// 2 products (Ah*B, Al*B). 2-stage cp.async, 61.4KB smem -> 2 CTAs/SM.
#define PITCH 40                 // fp16/row: 80B stride, conflict-free ldmatrix
#define TILE_B (128 * PITCH * 2) // 10240 bytes per (array, stage)
#define OFF_AH 0
#define OFF_AL TILE_B
#define OFF_BH (2*TILE_B)
#define STG (3*TILE_B)           // 30720
#define GSM_TOT (2*STG)          // 61440

__global__ __launch_bounds__(512) void gemm_mma_kernel(
    const __half* __restrict__ Ah, const __half* __restrict__ Al,
    const __half* __restrict__ Bh,
    float* __restrict__ Cd, const float* __restrict__ gbias, int mode)
{
    extern __shared__ __align__(16) char gsm[];
    const uint32_t su = smem_u32(gsm);
    const int tid = threadIdx.x, lane = tid & 31, warp = tid >> 5;
    const int wm = (warp & 3) * 32, wn = (warp >> 2) * 32;
    const int n0 = blockIdx.x * 128, bm = blockIdx.y * 128, bb = blockIdx.z;

    // staging: thread t -> row = t>>2 (0..127), 16B chunk = t&3
    const int s_r = tid >> 2, s_c = (tid & 3);
    const uint32_t s_off = (uint32_t)(s_r * (PITCH * 2) + s_c * 16);
    const size_t a_go = (size_t)(bm + s_r) * 256 + s_c * 8;
    const size_t b_go = ((size_t)bb * HWc + n0 + s_r) * 256 + s_c * 8;

    float acc[2][4][4];
#pragma unroll
    for (int i = 0; i < 2; i++)
#pragma unroll
        for (int j = 0; j < 4; j++)
#pragma unroll
            for (int k = 0; k < 4; k++) acc[i][j][k] = 0.0f;

    // prologue: stages 0 and 1
#pragma unroll
    for (int pre = 0; pre < 2; pre++) {
        const uint32_t sb = su + pre * STG;
        const int k0 = pre * 32;
        cpa16(sb + OFF_AH + s_off, Ah + a_go + k0);
        cpa16(sb + OFF_AL + s_off, Al + a_go + k0);
        cpa16(sb + OFF_BH + s_off, Bh + b_go + k0);
        CPA_COMMIT();
    }

    for (int it = 0; it < 8; it++) {
        if (it < 7) CPA_WAIT1(); else CPA_WAIT0();
        __syncthreads();
        const uint32_t sb = su + (it & 1) * STG;
#pragma unroll
        for (int ks = 0; ks < 2; ks++) {
            uint32_t ahf[2][4], alf[2][4], bhf[4][2];
#pragma unroll
            for (int mt = 0; mt < 2; mt++) {
                uint32_t ao = (uint32_t)(((wm + mt * 16 + (lane & 15)) * PITCH
                                          + ks * 16 + (lane >> 4) * 8) << 1);
                ldsm4(ahf[mt][0], ahf[mt][1], ahf[mt][2], ahf[mt][3], sb + OFF_AH + ao);
                ldsm4(alf[mt][0], alf[mt][1], alf[mt][2], alf[mt][3], sb + OFF_AL + ao);
            }
            // B: one ldsm4 covers two n-tiles (lane bit4 -> +8 rows, bit3 -> +8 cols)
#pragma unroll
            for (int ntp = 0; ntp < 2; ntp++) {
                uint32_t bo = (uint32_t)(((wn + ntp * 16 + ((lane >> 4) & 1) * 8 + (lane & 7)) * PITCH
                                          + ks * 16 + ((lane >> 3) & 1) * 8) << 1);
                ldsm4(bhf[2*ntp][0], bhf[2*ntp][1], bhf[2*ntp+1][0], bhf[2*ntp+1][1], sb + OFF_BH + bo);
            }
#pragma unroll
            for (int mt = 0; mt < 2; mt++)
#pragma unroll
                for (int nt = 0; nt < 4; nt++) {
                    mma16816h(acc[mt][nt], ahf[mt], bhf[nt]);
                    mma16816h(acc[mt][nt], alf[mt], bhf[nt]);
                }
        }
        if (it < 6) {
            __syncthreads();
            const int k0 = (it + 2) * 32;
            cpa16(sb + OFF_AH + s_off, Ah + a_go + k0);
            cpa16(sb + OFF_AL + s_off, Al + a_go + k0);
            cpa16(sb + OFF_BH + s_off, Bh + b_go + k0);
            CPA_COMMIT();
        }
    }

    // epilogue: fragment rows lane/4 (+8), cols 2*(lane%4)+{0,1}
    const int gr = lane >> 2, gc = (lane & 3) * 2;
#pragma unroll
    for (int mt = 0; mt < 2; mt++) {
        const int row0 = bm + wm + mt * 16 + gr;
        float* p0 = Cd + (size_t)bb * CHWc + (size_t)row0 * HWc + n0 + wn;
        float* p1 = p0 + (size_t)8 * HWc;
        if (mode == 0) {
#pragma unroll
            for (int nt = 0; nt < 4; nt++) {
                *(float2*)(p0 + nt * 8 + gc) = make_float2(acc[mt][nt][0], acc[mt][nt][1]);
                *(float2*)(p1 + nt * 8 + gc) = make_float2(acc[mt][nt][2], acc[mt][nt][3]);
            }
        } else {
            const float gb0 = gbias[row0], gb1 = gbias[row0 + 8];
#pragma unroll
            for (int nt = 0; nt < 4; nt++) {
                *(float2*)(p0 + nt * 8 + gc) =
                    make_float2(sigmoid_f(acc[mt][nt][0] + gb0), sigmoid_f(acc[mt][nt][1] + gb0));
                *(float2*)(p1 + nt * 8 + gc) =
                    make_float2(sigmoid_f(acc[mt][nt][2] + gb1), sigmoid_f(acc[mt][nt][3] + gb1));
            }
        }
    }
}

// ---------------- GroupNorm stats -> per-(b,c) affine ----------------
__global__ __launch_bounds__(1024) void gn_stats_kernel(const float* __restrict__ src,
                                                        const float* __restrict__ gamma,
                                                        const float* __restrict__ beta,
                                                        float* __restrict__ ss)
{
    const int g = blockIdx.x, b = blockIdx.y, tid = threadIdx.x;
    const float4* p = (const float4*)(src + (size_t)b * CHWc + (size_t)g * 16 * HWc);
    float s = 0.0f, s2 = 0.0f;
    const int n4 = 16 * HWc / 4;
    for (int i = tid; i < n4; i += 1024) {
        float4 v = p[i];
        s  += v.x + v.y + v.z + v.w;
        s2 += v.x * v.x + v.y * v.y + v.z * v.z + v.w * v.w;
    }
#pragma unroll
    for (int off = 16; off > 0; off >>= 1) {
        s  += __shfl_xor_sync(0xffffffffu, s, off);
        s2 += __shfl_xor_sync(0xffffffffu, s2, off);
    }
    __shared__ float ws[32], ws2[32];
    __shared__ float mean_s, rstd_s;
    const int wid = tid >> 5, lane = tid & 31;
    if (lane == 0) { ws[wid] = s; ws2[wid] = s2; }
    __syncthreads();
    if (tid < 32) {
        float ts = ws[tid], ts2 = ws2[tid];
#pragma unroll
        for (int off = 16; off > 0; off >>= 1) {
            ts  += __shfl_xor_sync(0xffffffffu, ts, off);
            ts2 += __shfl_xor_sync(0xffffffffu, ts2, off);
        }
        if (tid == 0) {
            const float inv = 1.0f / (16.0f * HWc);
            float mu  = ts * inv;
            float var = ts2 * inv - mu * mu;
            mean_s = mu;
            rstd_s = rsqrtf(var + 1e-5f);
        }
    }
    __syncthreads();
    if (tid < 16) {
        int c = g * 16 + tid;
        float sc = rstd_s * gamma[c];
        ss[(b * Cn + c) * 2 + 0] = sc;
        ss[(b * Cn + c) * 2 + 1] = beta[c] - mean_s * sc;
    }
}

// ---------------- horizontal scans: warp-per-row parallel scan ----------------
__global__ __launch_bounds__(256) void scan_w_kernel(const float* __restrict__ ap,
                                                     const float* __restrict__ bp,
                                                     const float* __restrict__ cp,
                                                     const float* __restrict__ dp)
{
    const int gw = blockIdx.x * 8 + (threadIdx.x >> 5);
    const int lane = threadIdx.x & 31;
    const int bc = gw / Hn;
    const int c  = bc & (Cn - 1);
    const float2 sc = *(const float2*)&g_ss1[bc * 2];
    const float a0 = sigmoid_f(ap[c]),    b0 = bp[c],    c0 = cp[c],    d0 = dp[c];
    const float a1 = sigmoid_f(ap[Cn+c]), b1 = bp[Cn+c], c1 = cp[Cn+c], d1 = dp[Cn+c];
    const float* xr = g_xp + (size_t)gw * Wn;

    float x0 = 0.f, x1 = 0.f, x2 = 0.f, x3 = 0.f;
    if (lane < 24) {
        float4 v = *(const float4*)(xr + lane * 4);
        x0 = silu_f(fmaf(v.x, sc.x, sc.y));
        x1 = silu_f(fmaf(v.y, sc.x, sc.y));
        x2 = silu_f(fmaf(v.z, sc.x, sc.y));
        x3 = silu_f(fmaf(v.w, sc.x, sc.y));
    }
    float a0_4 = (a0 * a0) * (a0 * a0);
    float S = b0 * x0;
    S = fmaf(a0, S, b0 * x1); S = fmaf(a0, S, b0 * x2); S = fmaf(a0, S, b0 * x3);
    float P = a0_4;
#pragma unroll
    for (int off = 1; off < 32; off <<= 1) {
        float Sp = __shfl_up_sync(0xffffffffu, S, off);
        float Pp = __shfl_up_sync(0xffffffffu, P, off);
        if (lane >= off) { S = fmaf(Sp, P, S); P *= Pp; }
    }
    float Hin = __shfl_up_sync(0xffffffffu, S, 1);
    if (lane == 0) Hin = 0.f;
    float hh = Hin;
    hh = fmaf(a0, hh, b0 * x0); float y0 = fmaf(c0, hh, d0 * x0);
    hh = fmaf(a0, hh, b0 * x1); float y1 = fmaf(c0, hh, d0 * x1);
    hh = fmaf(a0, hh, b0 * x2); float y2 = fmaf(c0, hh, d0 * x2);
    hh = fmaf(a0, hh, b0 * x3); float y3 = fmaf(c0, hh, d0 * x3);
    float a1_4 = (a1 * a1) * (a1 * a1);
    float S2 = b1 * x3;
    S2 = fmaf(a1, S2, b1 * x2); S2 = fmaf(a1, S2, b1 * x1); S2 = fmaf(a1, S2, b1 * x0);
    float P2 = a1_4;
    if (lane >= 24) { S2 = 0.f; P2 = 1.f; }
#pragma unroll
    for (int off = 1; off < 32; off <<= 1) {
        float Sp = __shfl_down_sync(0xffffffffu, S2, off);
        float Pp = __shfl_down_sync(0xffffffffu, P2, off);
        if (lane + off < 32) { S2 = fmaf(Sp, P2, S2); P2 *= Pp; }
    }
    float Hin2 = __shfl_down_sync(0xffffffffu, S2, 1);
    if (lane == 31) Hin2 = 0.f;
    hh = Hin2;
    hh = fmaf(a1, hh, b1 * x3); y3 += fmaf(c1, hh, d1 * x3);
    hh = fmaf(a1, hh, b1 * x2); y2 += fmaf(c1, hh, d1 * x2);
    hh = fmaf(a1, hh, b1 * x1); y1 += fmaf(c1, hh, d1 * x1);
    hh = fmaf(a1, hh, b1 * x0); y0 += fmaf(c1, hh, d1 * x0);

    if (lane < 24)
        *(float4*)(g_sw + (size_t)gw * Wn + lane * 4) = make_float4(y0, y1, y2, y3);
}

// ---------------- vertical scans: block per (b,c), thread per column ----------------
__global__ __launch_bounds__(96) void scan_h_kernel(const float* __restrict__ ap,
                                                    const float* __restrict__ bp,
                                                    const float* __restrict__ cp,
                                                    const float* __restrict__ dp)
{
    __shared__ float ytmp[HWc];   // 36 KB
    const int bc = blockIdx.x;
    const int c  = bc & (Cn - 1);
    const int tid = threadIdx.x;
    const float2 sc = *(const float2*)&g_ss1[bc * 2];
    const size_t base = (size_t)bc * HWc;

    const float a2 = sigmoid_f(ap[2*Cn+c]), b2 = bp[2*Cn+c], c2 = cp[2*Cn+c], d2 = dp[2*Cn+c];
    const float a3 = sigmoid_f(ap[3*Cn+c]), b3 = bp[3*Cn+c], c3 = cp[3*Cn+c], d3 = dp[3*Cn+c];
    const int w = tid;
    float hs = 0.f;
#pragma unroll 4
    for (int hhi = Hn - 1; hhi >= 0; hhi--) {
        float xv = silu_f(fmaf(g_xp[base + hhi * Wn + w], sc.x, sc.y));
        hs = fmaf(a3, hs, b3 * xv);
        ytmp[hhi * Wn + w] = fmaf(c3, hs, d3 * xv);
    }
    hs = 0.f;
#pragma unroll 4
    for (int hhi = 0; hhi < Hn; hhi++) {
        float xv = silu_f(fmaf(g_xp[base + hhi * Wn + w], sc.x, sc.y));
        hs = fmaf(a2, hs, b2 * xv);
        g_sh[base + hhi * Wn + w] = fmaf(c2, hs, d2 * xv) + ytmp[hhi * Wn + w];
    }
}

// ---------------- fused = 0.25*(sw+sh)*gate, 3x3 depthwise SAME conv ----------------
__global__ __launch_bounds__(256) void fuse_dw_kernel(const float* __restrict__ dww)
{
    __shared__ float ft[34 * 36];
    const int bc = blockIdx.z;
    const int h0 = blockIdx.y * 32, w0 = blockIdx.x * 32;
    const int c = bc & (Cn - 1);
    const size_t base = (size_t)bc * HWc;
    const int tid = threadIdx.x;

    for (int i = tid; i < 34 * 34; i += 256) {
        int r = i / 34, cc = i - r * 34;
        int gh = h0 - 1 + r, gw = w0 - 1 + cc;
        float v = 0.0f;
        if ((unsigned)gh < (unsigned)Hn && (unsigned)gw < (unsigned)Wn) {
            size_t idx = base + gh * Wn + gw;
            v = 0.25f * (g_sw[idx] + g_sh[idx]) * g_gate[idx];
        }
        ft[r * 36 + cc] = v;
    }
    float kw[9];
#pragma unroll
    for (int j = 0; j < 9; j++) kw[j] = dww[c * 9 + j];
    __syncthreads();

    const int tx = tid & 31, ty0 = tid >> 5;
#pragma unroll
    for (int rr = 0; rr < 4; rr++) {
        int r = ty0 + rr * 8;
        float acc = 0.0f;
#pragma unroll
        for (int i = 0; i < 3; i++)
#pragma unroll
            for (int j = 0; j < 3; j++)
                acc = fmaf(ft[(r + i) * 36 + tx + j], kw[i * 3 + j], acc);
        g_fd[base + (size_t)(h0 + r) * Wn + w0 + tx] = acc;
    }
}

// ---------------- final: silu(affine(o1)) -> out ----------------
__global__ __launch_bounds__(256) void finalize_kernel(const float* __restrict__ src,
                                                       const float* __restrict__ ss,
                                                       float* __restrict__ out)
{
    int i4 = blockIdx.x * 256 + threadIdx.x;
    if (i4 >= TOTc / 4) return;
    int bc = i4 / (HWc / 4);
    float2 sc = *(const float2*)&ss[bc * 2];
    float4 v = ((const float4*)src)[i4];
    v.x = silu_f(fmaf(v.x, sc.x, sc.y));
    v.y = silu_f(fmaf(v.y, sc.x, sc.y));
    v.z = silu_f(fmaf(v.z, sc.x, sc.y));
    v.w = silu_f(fmaf(v.w, sc.x, sc.y));
    ((float4*)out)[i4] = v;
}

// ---------------- launch ----------------
extern "C" void kernel_launch(void* const* d_in, const int* in_sizes, int n_in,
                              void* d_out, int out_size)
{
    const float* x      = (const float*)d_in[0];
    const float* in_w   = (const float*)d_in[1];
    const float* gn1_w  = (const float*)d_in[2];
    const float* gn1_b  = (const float*)d_in[3];
    const float* a_p    = (const float*)d_in[4];
    const float* b_p    = (const float*)d_in[5];
    const float* c_p    = (const float*)d_in[6];
    const float* d_p    = (const float*)d_in[7];
    const float* gate_w = (const float*)d_in[8];
    const float* gate_b = (const float*)d_in[9];
    const float* dw_w   = (const float*)d_in[10];
    const float* pw_w   = (const float*)d_in[11];
    const float* gn2_w  = (const float*)d_in[12];
    const float* gn2_b  = (const float*)d_in[13];
    float* out = (float*)d_out;

    float *p_xp, *p_gate, *p_fd, *p_o1, *p_ss1, *p_ss2;
    __half *p_bt, *p_ah, *p_al;
    cudaGetSymbolAddress((void**)&p_xp,   g_xp);
    cudaGetSymbolAddress((void**)&p_gate, g_gate);
    cudaGetSymbolAddress((void**)&p_fd,   g_fd);
    cudaGetSymbolAddress((void**)&p_o1,   g_o1);
    cudaGetSymbolAddress((void**)&p_ss1,  g_ss1);
    cudaGetSymbolAddress((void**)&p_ss2,  g_ss2);
    cudaGetSymbolAddress((void**)&p_bt,   g_bt);
    cudaGetSymbolAddress((void**)&p_ah,   g_ahh);
    cudaGetSymbolAddress((void**)&p_al,   g_all);

    cudaFuncSetAttribute(gemm_mma_kernel, cudaFuncAttributeMaxDynamicSharedMemorySize, GSM_TOT);

    dim3 gcv(HWc / 32, Cn / 32, Bn);
    dim3 bcv(32, 8);
    dim3 gmm(HWc / 128, Cn / 128, Bn);

    // convert all three weight matrices up front
    convA3_kernel<<<3 * Cn * Cn / 256, 256>>>(in_w, gate_w, pw_w, p_ah, p_al);

    // GEMM1: xp = in_w @ x
    convT_kernel<<<gcv, bcv>>>(x, p_bt, p_ss1, 0);
    gemm_mma_kernel<<<gmm, 512, GSM_TOT>>>(p_ah, p_al, p_bt, p_xp, gate_b, 0);
    gn_stats_kernel<<<dim3(16, Bn), 1024>>>(p_xp, gn1_w, gn1_b, p_ss1);

    // gate GEMM: gate = sigmoid(gate_w @ silu(affine(xp)) + b)
    convT_kernel<<<gcv, bcv>>>(p_xp, p_bt, p_ss1, 1);
    gemm_mma_kernel<<<gmm, 512, GSM_TOT>>>(p_ah + 65536, p_al + 65536, p_bt, p_gate, gate_b, 1);

    // scans + fuse + depthwise
    scan_w_kernel<<<Bn * Cn * Hn / 8, 256>>>(a_p, b_p, c_p, d_p);
    scan_h_kernel<<<Bn * Cn, 96>>>(a_p, b_p, c_p, d_p);
    fuse_dw_kernel<<<dim3(3, 3, Bn * Cn), 256>>>(dw_w);

    // GEMM3: o1 = pw_w @ fd
    convT_kernel<<<gcv, bcv>>>(p_fd, p_bt, p_ss1, 0);
    gemm_mma_kernel<<<gmm, 512, GSM_TOT>>>(p_ah + 131072, p_al + 131072, p_bt, p_o1, gate_b, 0);

    gn_stats_kernel<<<dim3(16, Bn), 1024>>>(p_o1, gn2_w, gn2_b, p_ss2);
    finalize_kernel<<<(TOTc / 4 + 255) / 256, 256>>>(p_o1, p_ss2, out);
}